// round 1
// baseline (speedup 1.0000x reference)
#include <cuda_runtime.h>
#include <cuda_bf16.h>

// Problem constants
#define T_DIM 1024
#define B_DIM 4
#define S_DIM 1024
#define E_DIM 1024
#define H_DIM 16
#define D_DIM 64
#define TB (T_DIM * B_DIM)   // 4096 rows for projections

// Scratch (device globals — no allocation allowed)
__device__ float g_Q[TB * E_DIM];
__device__ float g_K[TB * E_DIM];
__device__ float g_V[TB * E_DIM];
__device__ float g_Ctx[TB * E_DIM];

// ---------------------------------------------------------------------------
// zero kernel (avg_weights region is poisoned; we accumulate with atomics)
// ---------------------------------------------------------------------------
__global__ void __launch_bounds__(256) zero_kernel(float* __restrict__ p, int n4) {
    int i = blockIdx.x * blockDim.x + threadIdx.x;
    if (i < n4) ((float4*)p)[i] = make_float4(0.f, 0.f, 0.f, 0.f);
}

// ---------------------------------------------------------------------------
// SGEMM: C[M,N] = alpha * (A[M,K] @ W[N,K]^T + bias[N])
// 64x64 tile, BK=16, 256 threads, 4x4 register tile
// ---------------------------------------------------------------------------
__global__ void __launch_bounds__(256) sgemm_bias(
    const float* __restrict__ A, const float* __restrict__ W,
    const float* __restrict__ bias, float* __restrict__ C,
    int M, int N, int K, float alpha)
{
    __shared__ float As[16][68];
    __shared__ float Ws[16][68];
    const int tid = threadIdx.x;
    const int m0 = blockIdx.y * 64;
    const int n0 = blockIdx.x * 64;
    const int ty = tid >> 4;        // 0..15
    const int tx = tid & 15;        // 0..15
    const int lr = tid >> 2;        // 0..63
    const int lc = (tid & 3) << 2;  // 0,4,8,12

    float c[4][4] = {};
    const float* Aptr = A + (long)(m0 + lr) * K + lc;
    const float* Wptr = W + (long)(n0 + lr) * K + lc;

    for (int k0 = 0; k0 < K; k0 += 16) {
        float4 a4 = *(const float4*)(Aptr + k0);
        float4 w4 = *(const float4*)(Wptr + k0);
        As[lc + 0][lr] = a4.x; As[lc + 1][lr] = a4.y;
        As[lc + 2][lr] = a4.z; As[lc + 3][lr] = a4.w;
        Ws[lc + 0][lr] = w4.x; Ws[lc + 1][lr] = w4.y;
        Ws[lc + 2][lr] = w4.z; Ws[lc + 3][lr] = w4.w;
        __syncthreads();
        #pragma unroll
        for (int k = 0; k < 16; k++) {
            float a[4], bb[4];
            #pragma unroll
            for (int i = 0; i < 4; i++) a[i]  = As[k][ty * 4 + i];
            #pragma unroll
            for (int j = 0; j < 4; j++) bb[j] = Ws[k][tx * 4 + j];
            #pragma unroll
            for (int i = 0; i < 4; i++)
                #pragma unroll
                for (int j = 0; j < 4; j++)
                    c[i][j] += a[i] * bb[j];
        }
        __syncthreads();
    }

    #pragma unroll
    for (int i = 0; i < 4; i++) {
        int row = m0 + ty * 4 + i;
        #pragma unroll
        for (int j = 0; j < 4; j++) {
            int col = n0 + tx * 4 + j;
            C[(long)row * N + col] = alpha * (c[i][j] + bias[col]);
        }
    }
}

// ---------------------------------------------------------------------------
// Attention kernel: one block = (b, h, 16 T-rows). 256 threads.
// SMEM: Qs[16][68] | Ks[128][68] (reused for V) | Sc[16][1024] | Ms[1024]
// ---------------------------------------------------------------------------
#define ATTN_SMEM_FLOATS (16 * 68 + 128 * 68 + 16 * 1024 + 1024)
#define ATTN_SMEM_BYTES  (ATTN_SMEM_FLOATS * 4)

__global__ void __launch_bounds__(256) attn_kernel(
    const float* __restrict__ Q, const float* __restrict__ K,
    const float* __restrict__ V, const float* __restrict__ amask,
    const int* __restrict__ padmask, float* __restrict__ Ctx,
    float* __restrict__ avgw)
{
    extern __shared__ float sm[];
    float* Qs = sm;                      // [16][68]
    float* Ks = sm + 16 * 68;            // [128][68]
    float* Sc = Ks + 128 * 68;           // [16][1024]
    float* Ms = Sc + 16 * 1024;          // [1024]

    const int tid  = threadIdx.x;
    const int lane = tid & 31;
    const int wrp  = tid >> 5;           // 0..7
    const int t0   = blockIdx.x * 16;
    const int h    = blockIdx.y;
    const int b    = blockIdx.z;

    // ---- load Q tile and padding-mask addend ----
    for (int i = tid; i < 16 * 16; i += 256) {
        int r = i >> 4, d4 = (i & 15) << 2;
        *(float4*)&Qs[r * 68 + d4] =
            *(const float4*)&Q[((long)(t0 + r) * B_DIM + b) * E_DIM + h * D_DIM + d4];
    }
    for (int s = tid; s < S_DIM; s += 256)
        Ms[s] = padmask[b * S_DIM + s] ? -1e30f : 0.0f;
    __syncthreads();

    // ---- scores: Sc[r][s] = q_r . k_s + attn_mask + pad ----
    for (int s0 = 0; s0 < S_DIM; s0 += 128) {
        for (int i = tid; i < 128 * 16; i += 256) {
            int s = i >> 4, d4 = (i & 15) << 2;
            *(float4*)&Ks[s * 68 + d4] =
                *(const float4*)&K[((long)(s0 + s) * B_DIM + b) * E_DIM + h * D_DIM + d4];
        }
        __syncthreads();

        float acc[2][4] = {};
        #pragma unroll
        for (int d4 = 0; d4 < D_DIM; d4 += 4) {
            float4 q0 = *(const float4*)&Qs[(wrp * 2 + 0) * 68 + d4];
            float4 q1 = *(const float4*)&Qs[(wrp * 2 + 1) * 68 + d4];
            #pragma unroll
            for (int j = 0; j < 4; j++) {
                float4 kv = *(const float4*)&Ks[(lane + 32 * j) * 68 + d4];
                acc[0][j] += q0.x * kv.x + q0.y * kv.y + q0.z * kv.z + q0.w * kv.w;
                acc[1][j] += q1.x * kv.x + q1.y * kv.y + q1.z * kv.z + q1.w * kv.w;
            }
        }
        #pragma unroll
        for (int i = 0; i < 2; i++) {
            int r = wrp * 2 + i;
            #pragma unroll
            for (int j = 0; j < 4; j++) {
                int s = lane + 32 * j;
                Sc[r * 1024 + s0 + s] = acc[i][j]
                    + amask[(long)(t0 + r) * S_DIM + s0 + s] + Ms[s0 + s];
            }
        }
        __syncthreads();
    }

    // ---- softmax (warp wrp owns rows 2*wrp, 2*wrp+1) + avg_weights ----
    #pragma unroll
    for (int ri = 0; ri < 2; ri++) {
        int r = wrp * 2 + ri;
        float* row = &Sc[r * 1024];
        float m = -1e30f;
        for (int s = lane; s < S_DIM; s += 32) m = fmaxf(m, row[s]);
        #pragma unroll
        for (int o = 16; o; o >>= 1) m = fmaxf(m, __shfl_xor_sync(0xffffffffu, m, o));
        float sum = 0.f;
        for (int s = lane; s < S_DIM; s += 32) {
            float e = __expf(row[s] - m);
            row[s] = e;
            sum += e;
        }
        #pragma unroll
        for (int o = 16; o; o >>= 1) sum += __shfl_xor_sync(0xffffffffu, sum, o);
        float inv = 1.0f / sum;
        float* aw = &avgw[((long)b * T_DIM + (t0 + r)) * S_DIM];
        for (int s = lane; s < S_DIM; s += 32) {
            float p = row[s] * inv;
            row[s] = p;
            atomicAdd(&aw[s], p * (1.0f / H_DIM));
        }
    }
    __syncthreads();

    // ---- PV: ctx[r][d] = sum_s p[r][s] * v[s][d] ----
    const int r  = tid >> 4;   // 0..15
    const int dg = tid & 15;   // d = dg*4
    float4 acc4 = make_float4(0.f, 0.f, 0.f, 0.f);
    for (int s0 = 0; s0 < S_DIM; s0 += 128) {
        for (int i = tid; i < 128 * 16; i += 256) {
            int s = i >> 4, d4 = (i & 15) << 2;
            *(float4*)&Ks[s * 68 + d4] =
                *(const float4*)&V[((long)(s0 + s) * B_DIM + b) * E_DIM + h * D_DIM + d4];
        }
        __syncthreads();
        #pragma unroll 4
        for (int s = 0; s < 128; s++) {
            float p  = Sc[r * 1024 + s0 + s];
            float4 v = *(const float4*)&Ks[s * 68 + dg * 4];
            acc4.x += p * v.x; acc4.y += p * v.y;
            acc4.z += p * v.z; acc4.w += p * v.w;
        }
        __syncthreads();
    }
    *(float4*)&Ctx[((long)(t0 + r) * B_DIM + b) * E_DIM + h * D_DIM + dg * 4] = acc4;
}

// ---------------------------------------------------------------------------
extern "C" void kernel_launch(void* const* d_in, const int* in_sizes, int n_in,
                              void* d_out, int out_size) {
    const float* query = (const float*)d_in[0];   // [T,B,E]
    const float* key   = (const float*)d_in[1];   // [S,B,E]
    const float* value = (const float*)d_in[2];   // [S,B,E]
    const int*   pad   = (const int*)d_in[3];     // [B,S] bool->int32
    const float* amask = (const float*)d_in[4];   // [T,S]
    const float* ipw   = (const float*)d_in[5];   // [3E,E]
    const float* ipb   = (const float*)d_in[6];   // [3E]
    const float* ow    = (const float*)d_in[7];   // [E,E]
    const float* ob    = (const float*)d_in[8];   // [E]

    float* out  = (float*)d_out;                  // [T,B,E]
    float* avgw = out + (long)T_DIM * B_DIM * E_DIM;  // [B,T,S]

    float *Qp, *Kp, *Vp, *Cp;
    cudaGetSymbolAddress((void**)&Qp, g_Q);
    cudaGetSymbolAddress((void**)&Kp, g_K);
    cudaGetSymbolAddress((void**)&Vp, g_V);
    cudaGetSymbolAddress((void**)&Cp, g_Ctx);

    cudaFuncSetAttribute(attn_kernel,
                         cudaFuncAttributeMaxDynamicSharedMemorySize,
                         ATTN_SMEM_BYTES);

    // zero avg_weights (accumulated via atomics)
    zero_kernel<<<(B_DIM * T_DIM * S_DIM / 4 + 255) / 256, 256>>>(
        avgw, B_DIM * T_DIM * S_DIM / 4);

    dim3 gproj(E_DIM / 64, TB / 64);
    // Q = (x Wq^T + bq) * scaling ; scaling = 1/sqrt(64) = 0.125
    sgemm_bias<<<gproj, 256>>>(query, ipw,                    ipb,            Qp,
                               TB, E_DIM, E_DIM, 0.125f);
    sgemm_bias<<<gproj, 256>>>(key,   ipw + E_DIM * E_DIM,     ipb + E_DIM,    Kp,
                               TB, E_DIM, E_DIM, 1.0f);
    sgemm_bias<<<gproj, 256>>>(value, ipw + 2 * E_DIM * E_DIM, ipb + 2 * E_DIM, Vp,
                               TB, E_DIM, E_DIM, 1.0f);

    attn_kernel<<<dim3(T_DIM / 16, H_DIM, B_DIM), 256, ATTN_SMEM_BYTES>>>(
        Qp, Kp, Vp, amask, pad, Cp, avgw);

    sgemm_bias<<<gproj, 256>>>(Cp, ow, ob, out, TB, E_DIM, E_DIM, 1.0f);
}

// round 2
// speedup vs baseline: 1.0249x; 1.0249x over previous
#include <cuda_runtime.h>
#include <cuda_bf16.h>

// Problem constants
#define T_DIM 1024
#define B_DIM 4
#define S_DIM 1024
#define E_DIM 1024
#define H_DIM 16
#define D_DIM 64
#define TB (T_DIM * B_DIM)   // 4096 rows for projections

// Scratch (device globals — no allocation allowed)
__device__ float g_Q[TB * E_DIM];
__device__ float g_K[TB * E_DIM];
__device__ float g_V[TB * E_DIM];
__device__ float g_Ctx[TB * E_DIM];
__device__ float g_P[(long)B_DIM * H_DIM * T_DIM * S_DIM];  // 256 MB normalized probs

// ---------------------------------------------------------------------------
// SGEMM: C[M,N] = alpha * (A[M,K] @ W[N,K]^T + bias[N])
// 128x128 tile, BK=8, 256 threads, 8x8 register tile, register prefetch
// ---------------------------------------------------------------------------
#define BM 128
#define BN 128
#define BK 8

__global__ void __launch_bounds__(256) sgemm128(
    const float* __restrict__ A, const float* __restrict__ W,
    const float* __restrict__ bias, float* __restrict__ C, float alpha)
{
    __shared__ float As[BK][BM];
    __shared__ float Bs[BK][BN];

    const int tid = threadIdx.x;
    const int m0 = blockIdx.y * BM;
    const int n0 = blockIdx.x * BN;

    const int lrow = tid >> 1;          // 0..127
    const int lcol = (tid & 1) * 4;     // 0 or 4
    const float* Ap = A + (long)(m0 + lrow) * E_DIM + lcol;
    const float* Wp = W + (long)(n0 + lrow) * E_DIM + lcol;

    const int tx = tid & 15;            // cols tx*8
    const int ty = tid >> 4;            // rows ty*8

    float c[8][8] = {};

    float4 a4 = *(const float4*)Ap;
    float4 w4 = *(const float4*)Wp;

    for (int k0 = 0; k0 < E_DIM; k0 += BK) {
        As[lcol + 0][lrow] = a4.x; As[lcol + 1][lrow] = a4.y;
        As[lcol + 2][lrow] = a4.z; As[lcol + 3][lrow] = a4.w;
        Bs[lcol + 0][lrow] = w4.x; Bs[lcol + 1][lrow] = w4.y;
        Bs[lcol + 2][lrow] = w4.z; Bs[lcol + 3][lrow] = w4.w;
        __syncthreads();

        if (k0 + BK < E_DIM) {
            a4 = *(const float4*)(Ap + k0 + BK);
            w4 = *(const float4*)(Wp + k0 + BK);
        }

        #pragma unroll
        for (int k = 0; k < BK; k++) {
            float a[8], b[8];
            *(float4*)&a[0] = *(const float4*)&As[k][ty * 8];
            *(float4*)&a[4] = *(const float4*)&As[k][ty * 8 + 4];
            *(float4*)&b[0] = *(const float4*)&Bs[k][tx * 8];
            *(float4*)&b[4] = *(const float4*)&Bs[k][tx * 8 + 4];
            #pragma unroll
            for (int i = 0; i < 8; i++)
                #pragma unroll
                for (int j = 0; j < 8; j++)
                    c[i][j] += a[i] * b[j];
        }
        __syncthreads();
    }

    #pragma unroll
    for (int i = 0; i < 8; i++) {
        int row = m0 + ty * 8 + i;
        #pragma unroll
        for (int j4 = 0; j4 < 8; j4 += 4) {
            int col = n0 + tx * 8 + j4;
            float4 o;
            o.x = alpha * (c[i][j4 + 0] + bias[col + 0]);
            o.y = alpha * (c[i][j4 + 1] + bias[col + 1]);
            o.z = alpha * (c[i][j4 + 2] + bias[col + 2]);
            o.w = alpha * (c[i][j4 + 3] + bias[col + 3]);
            *(float4*)&C[(long)row * E_DIM + col] = o;
        }
    }
}

// ---------------------------------------------------------------------------
// Attention kernel: one block = (b, h, 16 T-rows). 256 threads.
// ---------------------------------------------------------------------------
#define ATTN_SMEM_FLOATS (16 * 68 + 128 * 68 + 16 * 1024 + 1024)
#define ATTN_SMEM_BYTES  (ATTN_SMEM_FLOATS * 4)

__global__ void __launch_bounds__(256) attn_kernel(
    const float* __restrict__ Q, const float* __restrict__ K,
    const float* __restrict__ V, const float* __restrict__ amask,
    const int* __restrict__ padmask, float* __restrict__ Ctx,
    float* __restrict__ P)
{
    extern __shared__ float sm[];
    float* Qs = sm;                      // [16][68]
    float* Ks = sm + 16 * 68;            // [128][68]
    float* Sc = Ks + 128 * 68;           // [16][1024]
    float* Ms = Sc + 16 * 1024;          // [1024]

    const int tid  = threadIdx.x;
    const int lane = tid & 31;
    const int wrp  = tid >> 5;           // 0..7
    const int t0   = blockIdx.x * 16;
    const int h    = blockIdx.y;
    const int b    = blockIdx.z;

    for (int i = tid; i < 16 * 16; i += 256) {
        int r = i >> 4, d4 = (i & 15) << 2;
        *(float4*)&Qs[r * 68 + d4] =
            *(const float4*)&Q[((long)(t0 + r) * B_DIM + b) * E_DIM + h * D_DIM + d4];
    }
    for (int s = tid; s < S_DIM; s += 256)
        Ms[s] = padmask[b * S_DIM + s] ? -1e30f : 0.0f;
    __syncthreads();

    for (int s0 = 0; s0 < S_DIM; s0 += 128) {
        for (int i = tid; i < 128 * 16; i += 256) {
            int s = i >> 4, d4 = (i & 15) << 2;
            *(float4*)&Ks[s * 68 + d4] =
                *(const float4*)&K[((long)(s0 + s) * B_DIM + b) * E_DIM + h * D_DIM + d4];
        }
        __syncthreads();

        float acc[2][4] = {};
        #pragma unroll
        for (int d4 = 0; d4 < D_DIM; d4 += 4) {
            float4 q0 = *(const float4*)&Qs[(wrp * 2 + 0) * 68 + d4];
            float4 q1 = *(const float4*)&Qs[(wrp * 2 + 1) * 68 + d4];
            #pragma unroll
            for (int j = 0; j < 4; j++) {
                float4 kv = *(const float4*)&Ks[(lane + 32 * j) * 68 + d4];
                acc[0][j] += q0.x * kv.x + q0.y * kv.y + q0.z * kv.z + q0.w * kv.w;
                acc[1][j] += q1.x * kv.x + q1.y * kv.y + q1.z * kv.z + q1.w * kv.w;
            }
        }
        #pragma unroll
        for (int i = 0; i < 2; i++) {
            int r = wrp * 2 + i;
            #pragma unroll
            for (int j = 0; j < 4; j++) {
                int s = lane + 32 * j;
                Sc[r * 1024 + s0 + s] = acc[i][j]
                    + amask[(long)(t0 + r) * S_DIM + s0 + s] + Ms[s0 + s];
            }
        }
        __syncthreads();
    }

    #pragma unroll
    for (int ri = 0; ri < 2; ri++) {
        int r = wrp * 2 + ri;
        float* row = &Sc[r * 1024];
        float m = -1e30f;
        for (int s = lane; s < S_DIM; s += 32) m = fmaxf(m, row[s]);
        #pragma unroll
        for (int o = 16; o; o >>= 1) m = fmaxf(m, __shfl_xor_sync(0xffffffffu, m, o));
        float sum = 0.f;
        for (int s = lane; s < S_DIM; s += 32) {
            float e = __expf(row[s] - m);
            row[s] = e;
            sum += e;
        }
        #pragma unroll
        for (int o = 16; o; o >>= 1) sum += __shfl_xor_sync(0xffffffffu, sum, o);
        float inv = 1.0f / sum;
        float* pw = &P[(((long)b * H_DIM + h) * T_DIM + (t0 + r)) * S_DIM];
        for (int s = lane; s < S_DIM; s += 32) {
            float p = row[s] * inv;
            row[s] = p;
            pw[s] = p;
        }
    }
    __syncthreads();

    const int r  = tid >> 4;
    const int dg = tid & 15;
    float4 acc4 = make_float4(0.f, 0.f, 0.f, 0.f);
    for (int s0 = 0; s0 < S_DIM; s0 += 128) {
        for (int i = tid; i < 128 * 16; i += 256) {
            int s = i >> 4, d4 = (i & 15) << 2;
            *(float4*)&Ks[s * 68 + d4] =
                *(const float4*)&V[((long)(s0 + s) * B_DIM + b) * E_DIM + h * D_DIM + d4];
        }
        __syncthreads();
        #pragma unroll 4
        for (int s = 0; s < 128; s++) {
            float p  = Sc[r * 1024 + s0 + s];
            float4 v = *(const float4*)&Ks[s * 68 + dg * 4];
            acc4.x += p * v.x; acc4.y += p * v.y;
            acc4.z += p * v.z; acc4.w += p * v.w;
        }
        __syncthreads();
    }
    *(float4*)&Ctx[((long)(t0 + r) * B_DIM + b) * E_DIM + h * D_DIM + dg * 4] = acc4;
}

// ---------------------------------------------------------------------------
// Mean over heads: avgw[b][t][s] = (1/H) * sum_h P[b][h][t][s]
// ---------------------------------------------------------------------------
__global__ void __launch_bounds__(256) avg_heads_kernel(
    const float* __restrict__ P, float* __restrict__ avgw)
{
    long i = (long)blockIdx.x * blockDim.x + threadIdx.x;
    const long TS4 = (long)T_DIM * S_DIM / 4;
    int b = (int)(i / TS4);
    long rem = i % TS4;
    const float4* base = (const float4*)P + (long)b * H_DIM * TS4 + rem;
    float4 acc = make_float4(0.f, 0.f, 0.f, 0.f);
    #pragma unroll
    for (int h = 0; h < H_DIM; h++) {
        float4 v = base[(long)h * TS4];
        acc.x += v.x; acc.y += v.y; acc.z += v.z; acc.w += v.w;
    }
    const float inv = 1.0f / H_DIM;
    acc.x *= inv; acc.y *= inv; acc.z *= inv; acc.w *= inv;
    ((float4*)avgw)[i] = acc;
}

// ---------------------------------------------------------------------------
extern "C" void kernel_launch(void* const* d_in, const int* in_sizes, int n_in,
                              void* d_out, int out_size) {
    const float* query = (const float*)d_in[0];
    const float* key   = (const float*)d_in[1];
    const float* value = (const float*)d_in[2];
    const int*   pad   = (const int*)d_in[3];
    const float* amask = (const float*)d_in[4];
    const float* ipw   = (const float*)d_in[5];
    const float* ipb   = (const float*)d_in[6];
    const float* ow    = (const float*)d_in[7];
    const float* ob    = (const float*)d_in[8];

    float* out  = (float*)d_out;
    float* avgw = out + (long)T_DIM * B_DIM * E_DIM;

    float *Qp, *Kp, *Vp, *Cp, *Pp;
    cudaGetSymbolAddress((void**)&Qp, g_Q);
    cudaGetSymbolAddress((void**)&Kp, g_K);
    cudaGetSymbolAddress((void**)&Vp, g_V);
    cudaGetSymbolAddress((void**)&Cp, g_Ctx);
    cudaGetSymbolAddress((void**)&Pp, g_P);

    cudaFuncSetAttribute(attn_kernel,
                         cudaFuncAttributeMaxDynamicSharedMemorySize,
                         ATTN_SMEM_BYTES);

    dim3 gproj(E_DIM / BN, TB / BM);   // (8, 32)
    sgemm128<<<gproj, 256>>>(query, ipw,                     ipb,             Qp, 0.125f);
    sgemm128<<<gproj, 256>>>(key,   ipw + E_DIM * E_DIM,     ipb + E_DIM,     Kp, 1.0f);
    sgemm128<<<gproj, 256>>>(value, ipw + 2 * E_DIM * E_DIM, ipb + 2 * E_DIM, Vp, 1.0f);

    attn_kernel<<<dim3(T_DIM / 16, H_DIM, B_DIM), 256, ATTN_SMEM_BYTES>>>(
        Qp, Kp, Vp, amask, pad, Cp, Pp);

    avg_heads_kernel<<<(int)((long)B_DIM * T_DIM * S_DIM / 4 / 256), 256>>>(Pp, avgw);

    sgemm128<<<gproj, 256>>>(Cp, ow, ob, out, 1.0f);
}

// round 3
// speedup vs baseline: 2.4101x; 2.3516x over previous
#include <cuda_runtime.h>
#include <cstdint>

// Problem constants
#define T_DIM 1024
#define B_DIM 4
#define S_DIM 1024
#define E_DIM 1024
#define H_DIM 16
#define D_DIM 64
#define TB (T_DIM * B_DIM)

// Scratch (device globals — no allocation allowed)
__device__ float g_Q[TB * E_DIM];
__device__ float g_K[TB * E_DIM];
__device__ float g_V[TB * E_DIM];
__device__ float g_Ctx[TB * E_DIM];
__device__ float g_S[(long)B_DIM * H_DIM * T_DIM * S_DIM];   // scores -> probs (256 MB)

// ---------------------------------------------------------------------------
// tf32 helpers
// ---------------------------------------------------------------------------
__device__ __forceinline__ uint32_t f2tf(float x) {
    uint32_t r;
    asm("cvt.rna.tf32.f32 %0, %1;" : "=r"(r) : "f"(x));
    return r;
}

__device__ __forceinline__ void mma8(float* d, const uint32_t* a, const uint32_t* b) {
    asm volatile(
        "mma.sync.aligned.m16n8k8.row.col.f32.tf32.tf32.f32 "
        "{%0,%1,%2,%3}, {%4,%5,%6,%7}, {%8,%9}, {%0,%1,%2,%3};\n"
        : "+f"(d[0]), "+f"(d[1]), "+f"(d[2]), "+f"(d[3])
        : "r"(a[0]), "r"(a[1]), "r"(a[2]), "r"(a[3]), "r"(b[0]), "r"(b[1]));
}

#define PBK 32
#define LDA 132

// ---------------------------------------------------------------------------
// K1/K6: C[M=…,1024] = alpha*(A[M,1024] @ W[1024,1024]^T + bias)
// 128x128x32 tile, 8 warps (2m x 4n), warp tile 64x32, m16n8k8 tf32
// ---------------------------------------------------------------------------
__global__ void __launch_bounds__(256) gemm_tf32_bias(
    const float* __restrict__ A, const float* __restrict__ W,
    const float* __restrict__ bias, float* __restrict__ C, float alpha)
{
    __shared__ uint32_t As[PBK][LDA];
    __shared__ uint32_t Bs[PBK][LDA];
    const int tid = threadIdx.x, lane = tid & 31, wid = tid >> 5;
    const int wm = (wid >> 2) * 64, wn = (wid & 3) * 32;
    const int m0 = blockIdx.y * 128, n0 = blockIdx.x * 128;
    const int g = lane >> 2, tg = lane & 3;

    float acc[4][4][4];
    #pragma unroll
    for (int i = 0; i < 4; i++)
        #pragma unroll
        for (int j = 0; j < 4; j++)
            #pragma unroll
            for (int q = 0; q < 4; q++) acc[i][j][q] = 0.f;

    for (int k0 = 0; k0 < E_DIM; k0 += PBK) {
        #pragma unroll
        for (int p = 0; p < 4; p++) {
            int idx = tid + p * 256;
            int row = idx >> 3, kc = (idx & 7) << 2;
            float4 a4 = *(const float4*)(A + (long)(m0 + row) * E_DIM + k0 + kc);
            float4 w4 = *(const float4*)(W + (long)(n0 + row) * E_DIM + k0 + kc);
            As[kc + 0][row] = f2tf(a4.x); As[kc + 1][row] = f2tf(a4.y);
            As[kc + 2][row] = f2tf(a4.z); As[kc + 3][row] = f2tf(a4.w);
            Bs[kc + 0][row] = f2tf(w4.x); Bs[kc + 1][row] = f2tf(w4.y);
            Bs[kc + 2][row] = f2tf(w4.z); Bs[kc + 3][row] = f2tf(w4.w);
        }
        __syncthreads();
        #pragma unroll
        for (int ks = 0; ks < PBK; ks += 8) {
            uint32_t af[4][4], bf[4][2];
            #pragma unroll
            for (int mt = 0; mt < 4; mt++) {
                int r = wm + mt * 16 + g;
                af[mt][0] = As[ks + tg][r];
                af[mt][1] = As[ks + tg][r + 8];
                af[mt][2] = As[ks + tg + 4][r];
                af[mt][3] = As[ks + tg + 4][r + 8];
            }
            #pragma unroll
            for (int nt = 0; nt < 4; nt++) {
                int n = wn + nt * 8 + g;
                bf[nt][0] = Bs[ks + tg][n];
                bf[nt][1] = Bs[ks + tg + 4][n];
            }
            #pragma unroll
            for (int mt = 0; mt < 4; mt++)
                #pragma unroll
                for (int nt = 0; nt < 4; nt++)
                    mma8(acc[mt][nt], af[mt], bf[nt]);
        }
        __syncthreads();
    }

    #pragma unroll
    for (int mt = 0; mt < 4; mt++) {
        int r0 = m0 + wm + mt * 16 + g;
        #pragma unroll
        for (int nt = 0; nt < 4; nt++) {
            int c = n0 + wn + nt * 8 + 2 * tg;
            float2 bv = *(const float2*)(bias + c);
            float2 o0, o1;
            o0.x = alpha * (acc[mt][nt][0] + bv.x);
            o0.y = alpha * (acc[mt][nt][1] + bv.y);
            o1.x = alpha * (acc[mt][nt][2] + bv.x);
            o1.y = alpha * (acc[mt][nt][3] + bv.y);
            *(float2*)(C + (long)r0 * E_DIM + c) = o0;
            *(float2*)(C + (long)(r0 + 8) * E_DIM + c) = o1;
        }
    }
}

// ---------------------------------------------------------------------------
// K2: scores[z=(b,h)][T,S] = Q[b,h] @ K[b,h]^T + attn_mask + pad
// ---------------------------------------------------------------------------
__global__ void __launch_bounds__(256) score_kernel(
    const float* __restrict__ Q, const float* __restrict__ Kx,
    const float* __restrict__ amask, const int* __restrict__ pad,
    float* __restrict__ Sc)
{
    __shared__ uint32_t As[PBK][LDA];
    __shared__ uint32_t Bs[PBK][LDA];
    const int tid = threadIdx.x, lane = tid & 31, wid = tid >> 5;
    const int wm = (wid >> 2) * 64, wn = (wid & 3) * 32;
    const int t0 = blockIdx.y * 128, s0 = blockIdx.x * 128;
    const int z = blockIdx.z;
    const int b = z >> 4, h = z & 15;
    const int g = lane >> 2, tg = lane & 3;
    const float* Qb = Q + (long)b * E_DIM + h * D_DIM;
    const float* Kb = Kx + (long)b * E_DIM + h * D_DIM;

    float acc[4][4][4];
    #pragma unroll
    for (int i = 0; i < 4; i++)
        #pragma unroll
        for (int j = 0; j < 4; j++)
            #pragma unroll
            for (int q = 0; q < 4; q++) acc[i][j][q] = 0.f;

    #pragma unroll
    for (int k0 = 0; k0 < D_DIM; k0 += PBK) {
        #pragma unroll
        for (int p = 0; p < 4; p++) {
            int idx = tid + p * 256;
            int row = idx >> 3, kc = (idx & 7) << 2;
            float4 q4 = *(const float4*)(Qb + (long)(t0 + row) * (B_DIM * E_DIM) + k0 + kc);
            float4 k4 = *(const float4*)(Kb + (long)(s0 + row) * (B_DIM * E_DIM) + k0 + kc);
            As[kc + 0][row] = f2tf(q4.x); As[kc + 1][row] = f2tf(q4.y);
            As[kc + 2][row] = f2tf(q4.z); As[kc + 3][row] = f2tf(q4.w);
            Bs[kc + 0][row] = f2tf(k4.x); Bs[kc + 1][row] = f2tf(k4.y);
            Bs[kc + 2][row] = f2tf(k4.z); Bs[kc + 3][row] = f2tf(k4.w);
        }
        __syncthreads();
        #pragma unroll
        for (int ks = 0; ks < PBK; ks += 8) {
            uint32_t af[4][4], bf[4][2];
            #pragma unroll
            for (int mt = 0; mt < 4; mt++) {
                int r = wm + mt * 16 + g;
                af[mt][0] = As[ks + tg][r];
                af[mt][1] = As[ks + tg][r + 8];
                af[mt][2] = As[ks + tg + 4][r];
                af[mt][3] = As[ks + tg + 4][r + 8];
            }
            #pragma unroll
            for (int nt = 0; nt < 4; nt++) {
                int n = wn + nt * 8 + g;
                bf[nt][0] = Bs[ks + tg][n];
                bf[nt][1] = Bs[ks + tg + 4][n];
            }
            #pragma unroll
            for (int mt = 0; mt < 4; mt++)
                #pragma unroll
                for (int nt = 0; nt < 4; nt++)
                    mma8(acc[mt][nt], af[mt], bf[nt]);
        }
        __syncthreads();
    }

    float* So = Sc + (long)z * T_DIM * S_DIM;
    #pragma unroll
    for (int mt = 0; mt < 4; mt++) {
        int t = t0 + wm + mt * 16 + g;
        #pragma unroll
        for (int nt = 0; nt < 4; nt++) {
            int s = s0 + wn + nt * 8 + 2 * tg;
            float p0 = pad[b * S_DIM + s]     ? -1e30f : 0.f;
            float p1 = pad[b * S_DIM + s + 1] ? -1e30f : 0.f;
            float2 a0 = *(const float2*)(amask + (long)t * S_DIM + s);
            float2 a1 = *(const float2*)(amask + (long)(t + 8) * S_DIM + s);
            float2 o0, o1;
            o0.x = acc[mt][nt][0] + a0.x + p0;
            o0.y = acc[mt][nt][1] + a0.y + p1;
            o1.x = acc[mt][nt][2] + a1.x + p0;
            o1.y = acc[mt][nt][3] + a1.y + p1;
            *(float2*)(So + (long)t * S_DIM + s) = o0;
            *(float2*)(So + (long)(t + 8) * S_DIM + s) = o1;
        }
    }
}

// ---------------------------------------------------------------------------
// K3: row softmax in place (one warp per 1024-row)
// ---------------------------------------------------------------------------
__global__ void __launch_bounds__(256) softmax_kernel(float* __restrict__ Sc)
{
    const long row = (long)blockIdx.x * 8 + (threadIdx.x >> 5);
    const int lane = threadIdx.x & 31;
    float4* p = (float4*)(Sc + row * S_DIM);
    float4 v[8];
    float m = -1e30f;
    #pragma unroll
    for (int i = 0; i < 8; i++) {
        v[i] = p[lane + 32 * i];
        m = fmaxf(m, fmaxf(fmaxf(v[i].x, v[i].y), fmaxf(v[i].z, v[i].w)));
    }
    #pragma unroll
    for (int o = 16; o; o >>= 1) m = fmaxf(m, __shfl_xor_sync(0xffffffffu, m, o));
    float sum = 0.f;
    #pragma unroll
    for (int i = 0; i < 8; i++) {
        v[i].x = __expf(v[i].x - m); v[i].y = __expf(v[i].y - m);
        v[i].z = __expf(v[i].z - m); v[i].w = __expf(v[i].w - m);
        sum += v[i].x + v[i].y + v[i].z + v[i].w;
    }
    #pragma unroll
    for (int o = 16; o; o >>= 1) sum += __shfl_xor_sync(0xffffffffu, sum, o);
    float inv = 1.0f / sum;
    #pragma unroll
    for (int i = 0; i < 8; i++) {
        v[i].x *= inv; v[i].y *= inv; v[i].z *= inv; v[i].w *= inv;
        p[lane + 32 * i] = v[i];
    }
}

// ---------------------------------------------------------------------------
// K4: Ctx[b,h] (T x 64) = P[b,h] (T x S) @ V[b,h] (S x 64)
// 128x64x32 tile, 8 warps (4m x 2n), warp tile 32x32
// ---------------------------------------------------------------------------
#define VLDB 72

__global__ void __launch_bounds__(256) pv_kernel(
    const float* __restrict__ Sc, const float* __restrict__ V,
    float* __restrict__ Ctx)
{
    __shared__ uint32_t As[PBK][LDA];
    __shared__ uint32_t Bs[PBK][VLDB];
    const int tid = threadIdx.x, lane = tid & 31, wid = tid >> 5;
    const int wm = (wid >> 1) * 32, wn = (wid & 1) * 32;
    const int t0 = blockIdx.x * 128;
    const int z = blockIdx.z;
    const int b = z >> 4, h = z & 15;
    const int g = lane >> 2, tg = lane & 3;
    const float* Pb = Sc + (long)z * T_DIM * S_DIM;
    const float* Vb = V + (long)b * E_DIM + h * D_DIM;

    float acc[2][4][4];
    #pragma unroll
    for (int i = 0; i < 2; i++)
        #pragma unroll
        for (int j = 0; j < 4; j++)
            #pragma unroll
            for (int q = 0; q < 4; q++) acc[i][j][q] = 0.f;

    // prefetch registers
    float4 pa[4], pv[2];
    #pragma unroll
    for (int p = 0; p < 4; p++) {
        int idx = tid + p * 256;
        int row = idx >> 3, kc = (idx & 7) << 2;
        pa[p] = *(const float4*)(Pb + (long)(t0 + row) * S_DIM + kc);
    }
    #pragma unroll
    for (int p = 0; p < 2; p++) {
        int idx = tid + p * 256;
        int s = idx >> 4, d4 = (idx & 15) << 2;
        pv[p] = *(const float4*)(Vb + (long)s * (B_DIM * E_DIM) + d4);
    }

    for (int k0 = 0; k0 < S_DIM; k0 += PBK) {
        #pragma unroll
        for (int p = 0; p < 4; p++) {
            int idx = tid + p * 256;
            int row = idx >> 3, kc = (idx & 7) << 2;
            As[kc + 0][row] = f2tf(pa[p].x); As[kc + 1][row] = f2tf(pa[p].y);
            As[kc + 2][row] = f2tf(pa[p].z); As[kc + 3][row] = f2tf(pa[p].w);
        }
        #pragma unroll
        for (int p = 0; p < 2; p++) {
            int idx = tid + p * 256;
            int s = idx >> 4, d4 = (idx & 15) << 2;
            Bs[s][d4 + 0] = f2tf(pv[p].x); Bs[s][d4 + 1] = f2tf(pv[p].y);
            Bs[s][d4 + 2] = f2tf(pv[p].z); Bs[s][d4 + 3] = f2tf(pv[p].w);
        }
        __syncthreads();

        if (k0 + PBK < S_DIM) {
            #pragma unroll
            for (int p = 0; p < 4; p++) {
                int idx = tid + p * 256;
                int row = idx >> 3, kc = (idx & 7) << 2;
                pa[p] = *(const float4*)(Pb + (long)(t0 + row) * S_DIM + k0 + PBK + kc);
            }
            #pragma unroll
            for (int p = 0; p < 2; p++) {
                int idx = tid + p * 256;
                int s = idx >> 4, d4 = (idx & 15) << 2;
                pv[p] = *(const float4*)(Vb + (long)(k0 + PBK + s) * (B_DIM * E_DIM) + d4);
            }
        }

        #pragma unroll
        for (int ks = 0; ks < PBK; ks += 8) {
            uint32_t af[2][4], bf[4][2];
            #pragma unroll
            for (int mt = 0; mt < 2; mt++) {
                int r = wm + mt * 16 + g;
                af[mt][0] = As[ks + tg][r];
                af[mt][1] = As[ks + tg][r + 8];
                af[mt][2] = As[ks + tg + 4][r];
                af[mt][3] = As[ks + tg + 4][r + 8];
            }
            #pragma unroll
            for (int nt = 0; nt < 4; nt++) {
                int n = wn + nt * 8 + g;
                bf[nt][0] = Bs[ks + tg][n];
                bf[nt][1] = Bs[ks + tg + 4][n];
            }
            #pragma unroll
            for (int mt = 0; mt < 2; mt++)
                #pragma unroll
                for (int nt = 0; nt < 4; nt++)
                    mma8(acc[mt][nt], af[mt], bf[nt]);
        }
        __syncthreads();
    }

    #pragma unroll
    for (int mt = 0; mt < 2; mt++) {
        int t = t0 + wm + mt * 16 + g;
        #pragma unroll
        for (int nt = 0; nt < 4; nt++) {
            int d = wn + nt * 8 + 2 * tg;
            float2 o0, o1;
            o0.x = acc[mt][nt][0]; o0.y = acc[mt][nt][1];
            o1.x = acc[mt][nt][2]; o1.y = acc[mt][nt][3];
            *(float2*)(Ctx + (long)t * (B_DIM * E_DIM) + b * E_DIM + h * D_DIM + d) = o0;
            *(float2*)(Ctx + (long)(t + 8) * (B_DIM * E_DIM) + b * E_DIM + h * D_DIM + d) = o1;
        }
    }
}

// ---------------------------------------------------------------------------
// K5: avgw[b][t][s] = (1/H) * sum_h P[b][h][t][s]
// ---------------------------------------------------------------------------
__global__ void __launch_bounds__(256) avg_heads_kernel(
    const float* __restrict__ P, float* __restrict__ avgw)
{
    long i = (long)blockIdx.x * blockDim.x + threadIdx.x;
    const long TS4 = (long)T_DIM * S_DIM / 4;
    int b = (int)(i / TS4);
    long rem = i % TS4;
    const float4* base = (const float4*)P + (long)b * H_DIM * TS4 + rem;
    float4 acc = make_float4(0.f, 0.f, 0.f, 0.f);
    #pragma unroll
    for (int h = 0; h < H_DIM; h++) {
        float4 v = base[(long)h * TS4];
        acc.x += v.x; acc.y += v.y; acc.z += v.z; acc.w += v.w;
    }
    const float inv = 1.0f / H_DIM;
    acc.x *= inv; acc.y *= inv; acc.z *= inv; acc.w *= inv;
    ((float4*)avgw)[i] = acc;
}

// ---------------------------------------------------------------------------
extern "C" void kernel_launch(void* const* d_in, const int* in_sizes, int n_in,
                              void* d_out, int out_size) {
    const float* query = (const float*)d_in[0];
    const float* key   = (const float*)d_in[1];
    const float* value = (const float*)d_in[2];
    const int*   pad   = (const int*)d_in[3];
    const float* amask = (const float*)d_in[4];
    const float* ipw   = (const float*)d_in[5];
    const float* ipb   = (const float*)d_in[6];
    const float* ow    = (const float*)d_in[7];
    const float* ob    = (const float*)d_in[8];

    float* out  = (float*)d_out;
    float* avgw = out + (long)T_DIM * B_DIM * E_DIM;

    float *Qp, *Kp, *Vp, *Cp, *Sp;
    cudaGetSymbolAddress((void**)&Qp, g_Q);
    cudaGetSymbolAddress((void**)&Kp, g_K);
    cudaGetSymbolAddress((void**)&Vp, g_V);
    cudaGetSymbolAddress((void**)&Cp, g_Ctx);
    cudaGetSymbolAddress((void**)&Sp, g_S);

    dim3 gproj(E_DIM / 128, TB / 128);   // (8, 32)
    gemm_tf32_bias<<<gproj, 256>>>(query, ipw,                     ipb,             Qp, 0.125f);
    gemm_tf32_bias<<<gproj, 256>>>(key,   ipw + E_DIM * E_DIM,     ipb + E_DIM,     Kp, 1.0f);
    gemm_tf32_bias<<<gproj, 256>>>(value, ipw + 2 * E_DIM * E_DIM, ipb + 2 * E_DIM, Vp, 1.0f);

    score_kernel<<<dim3(S_DIM / 128, T_DIM / 128, B_DIM * H_DIM), 256>>>(
        Qp, Kp, amask, pad, Sp);

    softmax_kernel<<<(B_DIM * H_DIM * T_DIM) / 8, 256>>>(Sp);

    pv_kernel<<<dim3(T_DIM / 128, 1, B_DIM * H_DIM), 256>>>(Sp, Vp, Cp);

    avg_heads_kernel<<<(int)((long)B_DIM * T_DIM * S_DIM / 4 / 256), 256>>>(Sp, avgw);

    gemm_tf32_bias<<<gproj, 256>>>(Cp, ow, ob, out, 1.0f);
}